// round 2
// baseline (speedup 1.0000x reference)
#include <cuda_runtime.h>
#include <cstdint>

// ---------------------------------------------------------------------------
// HyperGANUpBlock: upsample2x -> conv3d(3^3, 256->128, per-sample W) -> IN+ReLU
//                  -> concat(skip) -> conv3d(3^3, 256->128) -> IN+ReLU
// Shapes: x[4,16,16,16,256], w1[4,3,3,3,256,128], w2[4,3,3,3,256,128],
//         skip[4,32,32,32,128], out[4,32,32,32,128] (fp32)
// ---------------------------------------------------------------------------

#define B_    4
#define S_    32           // output spatial extent per dim
#define SIN_  16           // input spatial extent per dim
#define CIN_  256
#define CMID_ 128
#define NTOT  (4u * 32u * 32u * 32u * 128u)   // 16,777,216

// Scratch (device globals: allocation-free, graph-capturable, deterministic)
__device__ float  g_y1 [NTOT];
__device__ float  g_y1n[NTOT];
__device__ float  g_y2 [NTOT];
__device__ float2 g_part[4096 * 128];   // per-(b,z,y) block partial {sum, sumsq} per co
__device__ float2 g_mr1[512];           // {mean, rstd} per (b, co)
__device__ float2 g_mr2[512];

// ---- packed f32x2 helpers (2x fp32 FMA throughput; ptxas won't emit these) ----
__device__ __forceinline__ unsigned long long pack_dup(float v) {
    unsigned long long r;
    asm("mov.b64 %0, {%1, %1};" : "=l"(r) : "f"(v));
    return r;
}
__device__ __forceinline__ void fma2(unsigned long long& d,
                                     unsigned long long a,
                                     unsigned long long b) {
    asm("fma.rn.f32x2 %0, %1, %2, %0;" : "+l"(d) : "l"(a), "l"(b));
}
__device__ __forceinline__ void unpack2(unsigned long long v, float& lo, float& hi) {
    asm("mov.b64 {%0, %1}, %2;" : "=f"(lo), "=f"(hi) : "l"(v));
}

// ---------------------------------------------------------------------------
// Conv kernel. One block per (b, z, y): computes all 32 x-positions x 128 Cout.
// PASS 0: input = upsampled x (read via >>1), writes g_y1.
// PASS 1: input = concat(g_y1n, skip) by channel, writes g_y2.
// Also emits per-block partial {sum, sumsq} per co into g_part (deterministic).
// ---------------------------------------------------------------------------
template <int PASS>
__global__ __launch_bounds__(256)
void conv_kernel(const float* __restrict__ in0,   // PASS0: x        (else unused)
                 const float* __restrict__ in1,   // PASS1: skip     (else unused)
                 const float* __restrict__ wgt)   // per-sample weights
{
    __shared__ float sw[3][16][128];   // [kw][ci][co] for current ci-chunk
    __shared__ float sin_[16][36];     // [ci][xpos 0..33], padded

    const int tid = threadIdx.x;
    const int blk = blockIdx.x;           // b*1024 + z*32 + y
    const int b   = blk >> 10;
    const int z   = (blk >> 5) & 31;
    const int y   = blk & 31;

    const int cg  = tid & 31;             // co group: co = 4*cg .. 4*cg+3
    const int xg  = tid >> 5;             // x group:  x  = 4*xg .. 4*xg+3
    const int x0  = xg * 4;
    const int co4 = cg * 4;

    unsigned long long acc[4][2];
    #pragma unroll
    for (int i = 0; i < 4; ++i) { acc[i][0] = 0ull; acc[i][1] = 0ull; }

    const float* wb = wgt + (size_t)b * 27 * 256 * 128;

    for (int dzy = 0; dzy < 9; ++dzy) {
        const int dz = dzy / 3 - 1;
        const int dy = dzy % 3 - 1;
        const int zz = z + dz;
        const int yy = y + dy;
        const bool rowok = ((unsigned)zz < 32u) && ((unsigned)yy < 32u);
        const int czz = zz < 0 ? 0 : zz;   // clamped (guarded by rowok at use)
        const int cyy = yy < 0 ? 0 : yy;

        const float* srcA = nullptr;       // PASS0 row base
        size_t sp = 0;                     // PASS1 spatial row index
        if constexpr (PASS == 0) {
            srcA = in0 + ((((size_t)b * 16 + (czz >> 1)) * 16 + (cyy >> 1)) * 16) * 256;
        } else {
            sp = (((size_t)b * 32 + czz) * 32 + cyy) * 32;
        }
        const float* wtap = wb + (size_t)((dz + 1) * 9 + (dy + 1) * 3) * 256 * 128;

        for (int ch = 0; ch < 16; ++ch) {          // 16 chunks of 16 input channels
            __syncthreads();

            // ---- load input row: 34 xpos x 16 ci ----
            if constexpr (PASS == 0) {
                const float* src = srcA + ch * 16;
                for (int i = tid; i < 544; i += 256) {
                    const int xpos = i >> 4, ci = i & 15, xx = xpos - 1;
                    float v = 0.f;
                    if (rowok && (unsigned)xx < 32u)
                        v = src[(xx >> 1) * 256 + ci];
                    sin_[ci][xpos] = v;
                }
            } else {
                const float* src = (ch < 8)
                    ? (g_y1n + sp * 128 + ch * 16)
                    : (in1   + sp * 128 + (ch - 8) * 16);
                for (int i = tid; i < 544; i += 256) {
                    const int xpos = i >> 4, ci = i & 15, xx = xpos - 1;
                    float v = 0.f;
                    if (rowok && (unsigned)xx < 32u)
                        v = src[(size_t)xx * 128 + ci];
                    sin_[ci][xpos] = v;
                }
            }

            // ---- load weights: 3 kw taps x 16 ci x 128 co (contiguous) ----
            #pragma unroll
            for (int kw = 0; kw < 3; ++kw) {
                const float4* wp = (const float4*)(wtap + ((size_t)kw * 256 + ch * 16) * 128);
                float4* dst = (float4*)&sw[kw][0][0];
                dst[tid]       = wp[tid];
                dst[tid + 256] = wp[tid + 256];
            }
            __syncthreads();

            // ---- compute: 16 ci x 3 kw x (4 x-pos x 4 co) via f32x2 ----
            #pragma unroll
            for (int ci = 0; ci < 16; ++ci) {
                unsigned long long inp[6];
                #pragma unroll
                for (int j = 0; j < 6; ++j) inp[j] = pack_dup(sin_[ci][x0 + j]);
                #pragma unroll
                for (int kw = 0; kw < 3; ++kw) {
                    const ulonglong2 wv = *(const ulonglong2*)&sw[kw][ci][co4];
                    #pragma unroll
                    for (int xi = 0; xi < 4; ++xi) {
                        fma2(acc[xi][0], inp[kw + xi], wv.x);
                        fma2(acc[xi][1], inp[kw + xi], wv.y);
                    }
                }
            }
        }
    }

    // ---- unpack + write output tile ----
    float yv[4][4];
    #pragma unroll
    for (int xi = 0; xi < 4; ++xi) {
        unpack2(acc[xi][0], yv[xi][0], yv[xi][1]);
        unpack2(acc[xi][1], yv[xi][2], yv[xi][3]);
    }
    float* dsty = (PASS == 0) ? g_y1 : g_y2;
    const size_t obase = (size_t)blk * 32 * 128;
    #pragma unroll
    for (int xi = 0; xi < 4; ++xi) {
        *(float4*)&dsty[obase + (size_t)(x0 + xi) * 128 + co4] =
            make_float4(yv[xi][0], yv[xi][1], yv[xi][2], yv[xi][3]);
    }

    // ---- per-block {sum, sumsq} per co (deterministic reduction) ----
    __syncthreads();                       // done reading sw; reuse as reduction buf
    float2* sred = (float2*)&sw[0][0][0];  // [8 xgroups][128 co]
    #pragma unroll
    for (int c = 0; c < 4; ++c) {
        float s = 0.f, q = 0.f;
        #pragma unroll
        for (int xi = 0; xi < 4; ++xi) { s += yv[xi][c]; q += yv[xi][c] * yv[xi][c]; }
        sred[xg * 128 + co4 + c] = make_float2(s, q);
    }
    __syncthreads();
    if (tid < 128) {
        float s = 0.f, q = 0.f;
        #pragma unroll
        for (int g = 0; g < 8; ++g) {
            const float2 v = sred[g * 128 + tid];
            s += v.x; q += v.y;
        }
        g_part[(size_t)blk * 128 + tid] = make_float2(s, q);
    }
}

// ---------------------------------------------------------------------------
// Reduce g_part (1024 blocks per (b,co)) -> mean / rstd
// ---------------------------------------------------------------------------
template <int WHICH>
__global__ __launch_bounds__(256)
void finalize_kernel()
{
    const int tid = threadIdx.x;
    const int co  = blockIdx.x & 127;
    const int b   = blockIdx.x >> 7;
    float s = 0.f, q = 0.f;
    for (int e = tid; e < 1024; e += 256) {
        const float2 v = g_part[((size_t)b * 1024 + e) * 128 + co];
        s += v.x; q += v.y;
    }
    __shared__ float ss[256], qq[256];
    ss[tid] = s; qq[tid] = q;
    __syncthreads();
    for (int st = 128; st > 0; st >>= 1) {
        if (tid < st) { ss[tid] += ss[tid + st]; qq[tid] += qq[tid + st]; }
        __syncthreads();
    }
    if (tid == 0) {
        const float inv  = 1.0f / 32768.0f;
        const float mean = ss[0] * inv;
        const float var  = qq[0] * inv - mean * mean;
        const float2 mr  = make_float2(mean, rsqrtf(var + 1e-5f));
        if (WHICH == 0) g_mr1[b * 128 + co] = mr;
        else            g_mr2[b * 128 + co] = mr;
    }
}

// ---------------------------------------------------------------------------
// Elementwise instance-norm + ReLU (float4 grid-stride over 16.7M elems)
// ---------------------------------------------------------------------------
__global__ __launch_bounds__(256)
void norm1_kernel()
{
    const size_t idx = (size_t)blockIdx.x * 256 + threadIdx.x;  // 4,194,304 total
    const size_t e   = idx * 4;
    const int b  = (int)(e >> 22);
    const int co = (int)(e & 127);
    const float2* mr = g_mr1 + b * 128 + co;
    const float4 v = *(const float4*)&g_y1[e];
    const float2 m0 = mr[0], m1 = mr[1], m2 = mr[2], m3 = mr[3];
    float4 o;
    o.x = fmaxf(0.f, (v.x - m0.x) * m0.y);
    o.y = fmaxf(0.f, (v.y - m1.x) * m1.y);
    o.z = fmaxf(0.f, (v.z - m2.x) * m2.y);
    o.w = fmaxf(0.f, (v.w - m3.x) * m3.y);
    *(float4*)&g_y1n[e] = o;
}

__global__ __launch_bounds__(256)
void norm2_kernel(float* __restrict__ out)
{
    const size_t idx = (size_t)blockIdx.x * 256 + threadIdx.x;
    const size_t e   = idx * 4;
    const int b  = (int)(e >> 22);
    const int co = (int)(e & 127);
    const float2* mr = g_mr2 + b * 128 + co;
    const float4 v = *(const float4*)&g_y2[e];
    const float2 m0 = mr[0], m1 = mr[1], m2 = mr[2], m3 = mr[3];
    float4 o;
    o.x = fmaxf(0.f, (v.x - m0.x) * m0.y);
    o.y = fmaxf(0.f, (v.y - m1.x) * m1.y);
    o.z = fmaxf(0.f, (v.z - m2.x) * m2.y);
    o.w = fmaxf(0.f, (v.w - m3.x) * m3.y);
    *(float4*)&out[e] = o;
}

// ---------------------------------------------------------------------------
extern "C" void kernel_launch(void* const* d_in, const int* in_sizes, int n_in,
                              void* d_out, int out_size)
{
    const float* x    = (const float*)d_in[0];   // [4,16,16,16,256]
    const float* w1   = (const float*)d_in[1];   // [4,3,3,3,256,128]
    const float* w2   = (const float*)d_in[2];   // [4,3,3,3,256,128]
    const float* skip = (const float*)d_in[3];   // [4,32,32,32,128]
    float* out = (float*)d_out;                  // [4,32,32,32,128]
    (void)in_sizes; (void)n_in; (void)out_size;

    conv_kernel<0><<<4096, 256>>>(x, nullptr, w1);
    finalize_kernel<0><<<512, 256>>>();
    norm1_kernel<<<16384, 256>>>();
    conv_kernel<1><<<4096, 256>>>(nullptr, skip, w2);
    finalize_kernel<1><<<512, 256>>>();
    norm2_kernel<<<16384, 256>>>(out);
}

// round 5
// speedup vs baseline: 2.7439x; 2.7439x over previous
#include <cuda_runtime.h>
#include <cstdint>

// ===========================================================================
// HyperGANUpBlock via implicit GEMM on mma.sync tf32 (portable sm_100 path;
// tcgen05 unavailable: toolchain targets sm_100 without the 'a' feature set).
// x[4,16,16,16,256] -> upsample -> conv1(3^3,256->128,per-sample) -> IN+ReLU
// -> concat(skip[4,32,32,32,128]) -> conv2(3^3,256->128) -> IN+ReLU -> out
// ===========================================================================

#define SP    (34*34*34)         // 39304 padded spatial positions per sample
#define NTOT  (4u*32768u*128u)   // 16,777,216 output elems

// ---- scratch (device globals: zero-init at load; halos never written) -----
__device__ float  g_pin1[(size_t)4 * SP * 256];   // padded conv1 input (tf32-rounded)
__device__ float  g_pin2[(size_t)4 * SP * 256];   // padded conv2 input (y1n | skip)
__device__ float  g_y1  [NTOT];                   // conv1 raw output (unpadded)
__device__ float  g_y2  [NTOT];
__device__ float  g_wT1 [(size_t)4 * 27 * 128 * 256];  // [b][tap][co][ci] tf32-rounded
__device__ float  g_wT2 [(size_t)4 * 27 * 128 * 256];
__device__ float2 g_part[512 * 128];
__device__ float2 g_mr1 [512];
__device__ float2 g_mr2 [512];

// ---------------------------------------------------------------------------
__device__ __forceinline__ float tf32r(float v) {
    uint32_t u;
    asm("cvt.rna.tf32.f32 %0, %1;" : "=r"(u) : "f"(v));
    return __uint_as_float(u);
}
__device__ __forceinline__ void cpa16(uint32_t dst, const void* src) {
    asm volatile("cp.async.cg.shared.global [%0], [%1], 16;" :: "r"(dst), "l"(src));
}
__device__ __forceinline__ void mma_tf32(float* c, const uint32_t* a, const uint32_t* b) {
    asm volatile(
        "mma.sync.aligned.m16n8k8.row.col.f32.tf32.tf32.f32 "
        "{%0,%1,%2,%3}, {%4,%5,%6,%7}, {%8,%9}, {%0,%1,%2,%3};"
        : "+f"(c[0]), "+f"(c[1]), "+f"(c[2]), "+f"(c[3])
        : "r"(a[0]), "r"(a[1]), "r"(a[2]), "r"(a[3]), "r"(b[0]), "r"(b[1]));
}

// ===========================================================================
// conv as GEMM: grid (308 Mtiles, 4 samples), block 256 = 8 warps.
// Block: M=128 contiguous padded positions x N=128 co; K = 27 taps * 256 ci,
// consumed in 216 chunks of 32 (tap-major, chunks never straddle a tap).
// Smem tiles stride 36 floats -> all fragment LDS are bank-conflict-free.
// ===========================================================================
#define KTILE    32
#define STRIDE   36
#define TILE_F   (128 * STRIDE)          // floats per (A or B) tile = 4608
#define SMEM_F   (4 * TILE_F)            // 2 stages x (A+B) = 18432 floats (72KB)

__global__ __launch_bounds__(256, 2)
void conv_mma_kernel(const float* __restrict__ pin,   // padded input [4*SP][256]
                     const float* __restrict__ wT,    // [b][27][128 co][256 ci]
                     float* __restrict__ yout)        // [4][32768][128]
{
    extern __shared__ float smem[];
    const uint32_t smb = (uint32_t)__cvta_generic_to_shared(smem);
    const int tid = threadIdx.x;
    const int wid = tid >> 5, lane = tid & 31;
    const int gr = lane >> 2, tc = lane & 3;       // mma fragment coords
    const int warp_m = wid >> 1, warp_n = wid & 1; // 4 x 2 warp grid
    const int sbase = blockIdx.x * 128;            // padded position base
    const int bq    = blockIdx.y;                  // sample

    float acc[2][8][4];
    #pragma unroll
    for (int mt = 0; mt < 2; ++mt)
        #pragma unroll
        for (int nt = 0; nt < 8; ++nt)
            #pragma unroll
            for (int i = 0; i < 4; ++i) acc[mt][nt][i] = 0.f;

    const long  pos_lo = 0, pos_hi = 4L * SP - 1;

    // ---- async-load one K-chunk into stage stg ----
    auto issue = [&](int kc, int stg) {
        const int tap = kc >> 3, cib = (kc & 7) * 32;
        const int dz = tap / 9 - 1, dy = (tap / 3) % 3 - 1, dx = tap % 3 - 1;
        const long base_pos = (long)bq * SP + sbase + (dz * 1156 + dy * 34 + dx);
        const uint32_t sA = smb + (uint32_t)(stg * 2 * TILE_F) * 4;
        const uint32_t sB = sA + (uint32_t)TILE_F * 4;
        const float* wrow = wT + (((size_t)bq * 27 + tap) * 128) * 256 + cib;
        #pragma unroll
        for (int i = 0; i < 4; ++i) {
            const int c = tid + i * 256;
            const int r = c >> 3, s = c & 7;       // row 0..127, 16B segment 0..7
            long p = base_pos + r;                 // clamp: garbage rows are masked
            p = p < pos_lo ? pos_lo : (p > pos_hi ? pos_hi : p);
            cpa16(sA + (uint32_t)(r * STRIDE + s * 4) * 4, pin + p * 256 + cib + s * 4);
        }
        #pragma unroll
        for (int i = 0; i < 4; ++i) {
            const int c = tid + i * 256;
            const int r = c >> 3, s = c & 7;
            cpa16(sB + (uint32_t)(r * STRIDE + s * 4) * 4, wrow + (size_t)r * 256 + s * 4);
        }
        asm volatile("cp.async.commit_group;");
    };

    issue(0, 0);
    for (int kc = 0; kc < 216; ++kc) {
        const int buf = kc & 1;
        if (kc < 215) {
            issue(kc + 1, buf ^ 1);
            asm volatile("cp.async.wait_group 1;");
        } else {
            asm volatile("cp.async.wait_group 0;");
        }
        __syncthreads();

        const float* A = smem + buf * 2 * TILE_F;
        const float* B = A + TILE_F;
        #pragma unroll
        for (int kk = 0; kk < 4; ++kk) {           // 4 k8 steps per chunk
            uint32_t af[2][4];
            #pragma unroll
            for (int mt = 0; mt < 2; ++mt) {
                const float* ap = A + (warp_m * 32 + mt * 16 + gr) * STRIDE + kk * 8 + tc;
                af[mt][0] = __float_as_uint(ap[0]);
                af[mt][1] = __float_as_uint(ap[8 * STRIDE]);
                af[mt][2] = __float_as_uint(ap[4]);
                af[mt][3] = __float_as_uint(ap[8 * STRIDE + 4]);
            }
            uint32_t bf[8][2];
            #pragma unroll
            for (int nt = 0; nt < 8; ++nt) {
                const float* bp = B + (warp_n * 64 + nt * 8 + gr) * STRIDE + kk * 8 + tc;
                bf[nt][0] = __float_as_uint(bp[0]);
                bf[nt][1] = __float_as_uint(bp[4]);
            }
            #pragma unroll
            for (int mt = 0; mt < 2; ++mt)
                #pragma unroll
                for (int nt = 0; nt < 8; ++nt)
                    mma_tf32(acc[mt][nt], af[mt], bf[nt]);
        }
        __syncthreads();                           // before stage reuse
    }

    // ---- epilogue: write interior positions (masked by padded coords) ----
    #pragma unroll
    for (int mt = 0; mt < 2; ++mt) {
        #pragma unroll
        for (int h = 0; h < 2; ++h) {
            const int pos = sbase + warp_m * 32 + mt * 16 + gr + h * 8;
            const int z = pos / 1156;
            const int rr = pos - z * 1156;
            const int y = rr / 34;
            const int x = rr - y * 34;
            if (((unsigned)(z - 1) < 32u) && ((unsigned)(y - 1) < 32u) &&
                ((unsigned)(x - 1) < 32u)) {
                float* dst = yout +
                    ((size_t)((bq * 32 + (z - 1)) * 32 + (y - 1)) * 32 + (x - 1)) * 128;
                #pragma unroll
                for (int nt = 0; nt < 8; ++nt) {
                    const int col = warp_n * 64 + nt * 8 + 2 * tc;
                    *(float2*)(dst + col) =
                        make_float2(acc[mt][nt][h * 2], acc[mt][nt][h * 2 + 1]);
                }
            }
        }
    }
}

// ===========================================================================
// aux kernels (tf32 rounding applied where data feeds an MMA operand)
// ===========================================================================

// upsampled x -> padded g_pin1 interior (tf32-rounded)
__global__ __launch_bounds__(256)
void pad1_kernel(const float* __restrict__ x)
{
    const size_t i = (size_t)blockIdx.x * 256 + threadIdx.x;   // 8,388,608 float4s
    const int c4  = (int)(i & 63);
    const int pos = (int)((i >> 6) & 32767);
    const int b   = (int)(i >> 21);
    const int z = pos >> 10, y = (pos >> 5) & 31, xx = pos & 31;
    float4 v = *(const float4*)&x[((((size_t)b * 16 + (z >> 1)) * 16 + (y >> 1)) * 16
                                   + (xx >> 1)) * 256 + c4 * 4];
    v.x = tf32r(v.x); v.y = tf32r(v.y); v.z = tf32r(v.z); v.w = tf32r(v.w);
    const size_t sp = ((size_t)(z + 1) * 34 + (y + 1)) * 34 + (xx + 1);
    *(float4*)&g_pin1[((size_t)b * SP + sp) * 256 + c4 * 4] = v;
}

// w[b][tap][ci][co] -> wT[b][tap][co][ci], tf32-rounded  (grid 3456, block 256)
__global__ __launch_bounds__(256)
void wtrans_kernel(const float* __restrict__ w, float* __restrict__ wT)
{
    __shared__ float t[32][33];
    const int bt   = blockIdx.x;
    const int cot  = bt & 3;
    const int cit  = (bt >> 2) & 7;
    const int btap = bt >> 5;                 // 0..107
    const float* src = w  + (size_t)btap * 256 * 128;
    float*       dst = wT + (size_t)btap * 128 * 256;
    const int r = threadIdx.x >> 5, c = threadIdx.x & 31;
    #pragma unroll
    for (int i = 0; i < 4; ++i)
        t[r + 8 * i][c] = src[(size_t)(cit * 32 + r + 8 * i) * 128 + cot * 32 + c];
    __syncthreads();
    #pragma unroll
    for (int i = 0; i < 4; ++i)
        dst[(size_t)(cot * 32 + r + 8 * i) * 256 + cit * 32 + c] = tf32r(t[c][r + 8 * i]);
}

// per-(b, 256-position chunk) partial {sum,sumsq} per co  (grid 512, block 256)
template <int WHICH>
__global__ __launch_bounds__(256)
void stats_kernel()
{
    const float* src = WHICH ? g_y2 : g_y1;
    const int bc = blockIdx.x;
    const int b = bc >> 7, ch = bc & 127;
    const int co = threadIdx.x & 127, h = threadIdx.x >> 7;
    const size_t base = ((size_t)b * 32768 + ch * 256 + h * 128) * 128;
    float s = 0.f, q = 0.f;
    for (int i = 0; i < 128; ++i) {
        const float v = src[base + (size_t)i * 128 + co];
        s += v; q += v * v;
    }
    __shared__ float2 red[256];
    red[threadIdx.x] = make_float2(s, q);
    __syncthreads();
    if (h == 0) {
        const float2 o = red[threadIdx.x + 128];
        g_part[(size_t)bc * 128 + co] = make_float2(s + o.x, q + o.y);
    }
}

template <int WHICH>
__global__ __launch_bounds__(128)
void finalize_kernel()
{
    const int co = blockIdx.x & 127, b = blockIdx.x >> 7;
    const int t = threadIdx.x;
    const float2 v = g_part[((size_t)b * 128 + t) * 128 + co];
    __shared__ float ss[128], qq[128];
    ss[t] = v.x; qq[t] = v.y;
    __syncthreads();
    for (int st = 64; st > 0; st >>= 1) {
        if (t < st) { ss[t] += ss[t + st]; qq[t] += qq[t + st]; }
        __syncthreads();
    }
    if (t == 0) {
        const float inv  = 1.0f / 32768.0f;
        const float mean = ss[0] * inv;
        const float var  = qq[0] * inv - mean * mean;
        const float2 mr  = make_float2(mean, rsqrtf(var + 1e-5f));
        if (WHICH == 0) g_mr1[b * 128 + co] = mr;
        else            g_mr2[b * 128 + co] = mr;
    }
}

// IN+ReLU on y1 -> padded g_pin2[:,0:128]; skip -> g_pin2[:,128:256] (tf32-rounded)
__global__ __launch_bounds__(256)
void norm1cat_kernel(const float* __restrict__ skip)
{
    const size_t i = (size_t)blockIdx.x * 256 + threadIdx.x;   // 8,388,608 float4s
    const int c4  = (int)(i & 63);
    const int pos = (int)((i >> 6) & 32767);
    const int b   = (int)(i >> 21);
    const int col = c4 * 4;
    float4 v;
    if (col < 128) {
        v = *(const float4*)&g_y1[((size_t)b * 32768 + pos) * 128 + col];
        const float2* mr = g_mr1 + b * 128 + col;
        const float2 m0 = mr[0], m1 = mr[1], m2 = mr[2], m3 = mr[3];
        v.x = fmaxf(0.f, (v.x - m0.x) * m0.y);
        v.y = fmaxf(0.f, (v.y - m1.x) * m1.y);
        v.z = fmaxf(0.f, (v.z - m2.x) * m2.y);
        v.w = fmaxf(0.f, (v.w - m3.x) * m3.y);
    } else {
        v = *(const float4*)&skip[((size_t)b * 32768 + pos) * 128 + (col - 128)];
    }
    v.x = tf32r(v.x); v.y = tf32r(v.y); v.z = tf32r(v.z); v.w = tf32r(v.w);
    const int z = pos >> 10, y = (pos >> 5) & 31, xx = pos & 31;
    const size_t sp = ((size_t)(z + 1) * 34 + (y + 1)) * 34 + (xx + 1);
    *(float4*)&g_pin2[((size_t)b * SP + sp) * 256 + col] = v;
}

// IN+ReLU on y2 -> out (full fp32, no rounding)
__global__ __launch_bounds__(256)
void norm2_kernel(float* __restrict__ out)
{
    const size_t idx = (size_t)blockIdx.x * 256 + threadIdx.x;
    const size_t e   = idx * 4;
    const int b  = (int)(e >> 22);
    const int co = (int)(e & 127);
    const float2* mr = g_mr2 + b * 128 + co;
    const float4 v = *(const float4*)&g_y2[e];
    const float2 m0 = mr[0], m1 = mr[1], m2 = mr[2], m3 = mr[3];
    float4 o;
    o.x = fmaxf(0.f, (v.x - m0.x) * m0.y);
    o.y = fmaxf(0.f, (v.y - m1.x) * m1.y);
    o.z = fmaxf(0.f, (v.z - m2.x) * m2.y);
    o.w = fmaxf(0.f, (v.w - m3.x) * m3.y);
    *(float4*)&out[e] = o;
}

// ===========================================================================
// host
// ===========================================================================
extern "C" void kernel_launch(void* const* d_in, const int* in_sizes, int n_in,
                              void* d_out, int out_size)
{
    const float* x    = (const float*)d_in[0];
    const float* w1   = (const float*)d_in[1];
    const float* w2   = (const float*)d_in[2];
    const float* skip = (const float*)d_in[3];
    float* out = (float*)d_out;
    (void)in_sizes; (void)n_in; (void)out_size;

    void *pin1 = nullptr, *pin2 = nullptr, *wT1 = nullptr, *wT2 = nullptr,
         *y1 = nullptr, *y2 = nullptr;
    if (cudaGetSymbolAddress(&pin1, g_pin1) != cudaSuccess) return;
    if (cudaGetSymbolAddress(&pin2, g_pin2) != cudaSuccess) return;
    if (cudaGetSymbolAddress(&wT1,  g_wT1)  != cudaSuccess) return;
    if (cudaGetSymbolAddress(&wT2,  g_wT2)  != cudaSuccess) return;
    if (cudaGetSymbolAddress(&y1,   g_y1)   != cudaSuccess) return;
    if (cudaGetSymbolAddress(&y2,   g_y2)   != cudaSuccess) return;

    static bool attr_done = false;
    if (!attr_done) {
        cudaFuncSetAttribute(conv_mma_kernel,
                             cudaFuncAttributeMaxDynamicSharedMemorySize,
                             SMEM_F * 4);
        attr_done = true;
    }

    pad1_kernel<<<32768, 256>>>(x);
    wtrans_kernel<<<3456, 256>>>(w1, (float*)wT1);
    wtrans_kernel<<<3456, 256>>>(w2, (float*)wT2);

    conv_mma_kernel<<<dim3(308, 4), 256, SMEM_F * 4>>>(
        (const float*)pin1, (const float*)wT1, (float*)y1);
    stats_kernel<0><<<512, 256>>>();
    finalize_kernel<0><<<512, 128>>>();
    norm1cat_kernel<<<32768, 256>>>(skip);

    conv_mma_kernel<<<dim3(308, 4), 256, SMEM_F * 4>>>(
        (const float*)pin2, (const float*)wT2, (float*)y2);
    stats_kernel<1><<<512, 256>>>();
    finalize_kernel<1><<<512, 128>>>();
    norm2_kernel<<<16384, 256>>>(out);
}

// round 6
// speedup vs baseline: 2.7599x; 1.0058x over previous
#include <cuda_runtime.h>
#include <cstdint>

// ===========================================================================
// HyperGANUpBlock via implicit GEMM on mma.sync tf32 (portable sm_100 path;
// tcgen05 unavailable: toolchain targets sm_100 without the 'a' feature set).
// x[4,16,16,16,256] -> upsample -> conv1(3^3,256->128,per-sample) -> IN+ReLU
// -> concat(skip[4,32,32,32,128]) -> conv2(3^3,256->128) -> IN+ReLU -> out
// ===========================================================================

#define SP    (34*34*34)         // 39304 padded spatial positions per sample
#define NTOT  (4u*32768u*128u)   // 16,777,216 output elems

// ---- scratch (device globals: zero-init at load; halos never written) -----
__device__ float  g_pin1[(size_t)4 * SP * 256];   // padded conv1 input (tf32-rounded)
__device__ float  g_pin2[(size_t)4 * SP * 256];   // padded conv2 input (y1n | skip)
__device__ float  g_y1  [NTOT];                   // conv1 raw output (unpadded)
__device__ float  g_y2  [NTOT];
__device__ float  g_wT1 [(size_t)4 * 27 * 128 * 256];  // [b][tap][co][ci] tf32-rounded
__device__ float  g_wT2 [(size_t)4 * 27 * 128 * 256];
__device__ float2 g_part[512 * 128];
__device__ float2 g_mr1 [512];
__device__ float2 g_mr2 [512];

// ---------------------------------------------------------------------------
__device__ __forceinline__ float tf32r(float v) {
    uint32_t u;
    asm("cvt.rna.tf32.f32 %0, %1;" : "=r"(u) : "f"(v));
    return __uint_as_float(u);
}
__device__ __forceinline__ void cpa16(uint32_t dst, const void* src) {
    asm volatile("cp.async.cg.shared.global [%0], [%1], 16;" :: "r"(dst), "l"(src));
}
__device__ __forceinline__ void mma_tf32(float* c, const uint32_t* a, const uint32_t* b) {
    asm volatile(
        "mma.sync.aligned.m16n8k8.row.col.f32.tf32.tf32.f32 "
        "{%0,%1,%2,%3}, {%4,%5,%6,%7}, {%8,%9}, {%0,%1,%2,%3};"
        : "+f"(c[0]), "+f"(c[1]), "+f"(c[2]), "+f"(c[3])
        : "r"(a[0]), "r"(a[1]), "r"(a[2]), "r"(a[3]), "r"(b[0]), "r"(b[1]));
}

// ===========================================================================
// conv as GEMM: grid (308 Mtiles, 4 samples), block 256 = 8 warps.
// Block: M=128 contiguous padded positions x N=128 co; K = 27 taps * 256 ci,
// consumed in 216 chunks of 32 (tap-major, chunks never straddle a tap).
// Smem tiles stride 36 floats -> all fragment LDS are bank-conflict-free.
// ===========================================================================
#define KTILE    32
#define STRIDE   36
#define TILE_F   (128 * STRIDE)          // floats per (A or B) tile = 4608
#define SMEM_F   (4 * TILE_F)            // 2 stages x (A+B) = 18432 floats (72KB)

__global__ __launch_bounds__(256, 2)
void conv_mma_kernel(const float* __restrict__ pin,   // padded input [4*SP][256]
                     const float* __restrict__ wT,    // [b][27][128 co][256 ci]
                     float* __restrict__ yout)        // [4][32768][128]
{
    extern __shared__ float smem[];
    const uint32_t smb = (uint32_t)__cvta_generic_to_shared(smem);
    const int tid = threadIdx.x;
    const int wid = tid >> 5, lane = tid & 31;
    const int gr = lane >> 2, tc = lane & 3;       // mma fragment coords
    const int warp_m = wid >> 1, warp_n = wid & 1; // 4 x 2 warp grid
    const int sbase = blockIdx.x * 128;            // padded position base
    const int bq    = blockIdx.y;                  // sample

    float acc[2][8][4];
    #pragma unroll
    for (int mt = 0; mt < 2; ++mt)
        #pragma unroll
        for (int nt = 0; nt < 8; ++nt)
            #pragma unroll
            for (int i = 0; i < 4; ++i) acc[mt][nt][i] = 0.f;

    const long  pos_lo = 0, pos_hi = 4L * SP - 1;

    // ---- async-load one K-chunk into stage stg ----
    auto issue = [&](int kc, int stg) {
        const int tap = kc >> 3, cib = (kc & 7) * 32;
        const int dz = tap / 9 - 1, dy = (tap / 3) % 3 - 1, dx = tap % 3 - 1;
        const long base_pos = (long)bq * SP + sbase + (dz * 1156 + dy * 34 + dx);
        const uint32_t sA = smb + (uint32_t)(stg * 2 * TILE_F) * 4;
        const uint32_t sB = sA + (uint32_t)TILE_F * 4;
        const float* wrow = wT + (((size_t)bq * 27 + tap) * 128) * 256 + cib;
        #pragma unroll
        for (int i = 0; i < 4; ++i) {
            const int c = tid + i * 256;
            const int r = c >> 3, s = c & 7;       // row 0..127, 16B segment 0..7
            long p = base_pos + r;                 // clamp: garbage rows are masked
            p = p < pos_lo ? pos_lo : (p > pos_hi ? pos_hi : p);
            cpa16(sA + (uint32_t)(r * STRIDE + s * 4) * 4, pin + p * 256 + cib + s * 4);
        }
        #pragma unroll
        for (int i = 0; i < 4; ++i) {
            const int c = tid + i * 256;
            const int r = c >> 3, s = c & 7;
            cpa16(sB + (uint32_t)(r * STRIDE + s * 4) * 4, wrow + (size_t)r * 256 + s * 4);
        }
        asm volatile("cp.async.commit_group;");
    };

    issue(0, 0);
    for (int kc = 0; kc < 216; ++kc) {
        const int buf = kc & 1;
        if (kc < 215) {
            issue(kc + 1, buf ^ 1);
            asm volatile("cp.async.wait_group 1;");
        } else {
            asm volatile("cp.async.wait_group 0;");
        }
        __syncthreads();

        const float* A = smem + buf * 2 * TILE_F;
        const float* B = A + TILE_F;
        #pragma unroll
        for (int kk = 0; kk < 4; ++kk) {           // 4 k8 steps per chunk
            uint32_t af[2][4];
            #pragma unroll
            for (int mt = 0; mt < 2; ++mt) {
                const float* ap = A + (warp_m * 32 + mt * 16 + gr) * STRIDE + kk * 8 + tc;
                af[mt][0] = __float_as_uint(ap[0]);
                af[mt][1] = __float_as_uint(ap[8 * STRIDE]);
                af[mt][2] = __float_as_uint(ap[4]);
                af[mt][3] = __float_as_uint(ap[8 * STRIDE + 4]);
            }
            uint32_t bf[8][2];
            #pragma unroll
            for (int nt = 0; nt < 8; ++nt) {
                const float* bp = B + (warp_n * 64 + nt * 8 + gr) * STRIDE + kk * 8 + tc;
                bf[nt][0] = __float_as_uint(bp[0]);
                bf[nt][1] = __float_as_uint(bp[4]);
            }
            #pragma unroll
            for (int mt = 0; mt < 2; ++mt)
                #pragma unroll
                for (int nt = 0; nt < 8; ++nt)
                    mma_tf32(acc[mt][nt], af[mt], bf[nt]);
        }
        __syncthreads();                           // before stage reuse
    }

    // ---- epilogue: write interior positions (masked by padded coords) ----
    #pragma unroll
    for (int mt = 0; mt < 2; ++mt) {
        #pragma unroll
        for (int h = 0; h < 2; ++h) {
            const int pos = sbase + warp_m * 32 + mt * 16 + gr + h * 8;
            const int z = pos / 1156;
            const int rr = pos - z * 1156;
            const int y = rr / 34;
            const int x = rr - y * 34;
            if (((unsigned)(z - 1) < 32u) && ((unsigned)(y - 1) < 32u) &&
                ((unsigned)(x - 1) < 32u)) {
                float* dst = yout +
                    ((size_t)((bq * 32 + (z - 1)) * 32 + (y - 1)) * 32 + (x - 1)) * 128;
                #pragma unroll
                for (int nt = 0; nt < 8; ++nt) {
                    const int col = warp_n * 64 + nt * 8 + 2 * tc;
                    *(float2*)(dst + col) =
                        make_float2(acc[mt][nt][h * 2], acc[mt][nt][h * 2 + 1]);
                }
            }
        }
    }
}

// ===========================================================================
// aux kernels (tf32 rounding applied where data feeds an MMA operand)
// ===========================================================================

// upsampled x -> padded g_pin1 interior (tf32-rounded)
__global__ __launch_bounds__(256)
void pad1_kernel(const float* __restrict__ x)
{
    const size_t i = (size_t)blockIdx.x * 256 + threadIdx.x;   // 8,388,608 float4s
    const int c4  = (int)(i & 63);
    const int pos = (int)((i >> 6) & 32767);
    const int b   = (int)(i >> 21);
    const int z = pos >> 10, y = (pos >> 5) & 31, xx = pos & 31;
    float4 v = *(const float4*)&x[((((size_t)b * 16 + (z >> 1)) * 16 + (y >> 1)) * 16
                                   + (xx >> 1)) * 256 + c4 * 4];
    v.x = tf32r(v.x); v.y = tf32r(v.y); v.z = tf32r(v.z); v.w = tf32r(v.w);
    const size_t sp = ((size_t)(z + 1) * 34 + (y + 1)) * 34 + (xx + 1);
    *(float4*)&g_pin1[((size_t)b * SP + sp) * 256 + c4 * 4] = v;
}

// w[b][tap][ci][co] -> wT[b][tap][co][ci], tf32-rounded  (grid 3456, block 256)
__global__ __launch_bounds__(256)
void wtrans_kernel(const float* __restrict__ w, float* __restrict__ wT)
{
    __shared__ float t[32][33];
    const int bt   = blockIdx.x;
    const int cot  = bt & 3;
    const int cit  = (bt >> 2) & 7;
    const int btap = bt >> 5;                 // 0..107
    const float* src = w  + (size_t)btap * 256 * 128;
    float*       dst = wT + (size_t)btap * 128 * 256;
    const int r = threadIdx.x >> 5, c = threadIdx.x & 31;
    #pragma unroll
    for (int i = 0; i < 4; ++i)
        t[r + 8 * i][c] = src[(size_t)(cit * 32 + r + 8 * i) * 128 + cot * 32 + c];
    __syncthreads();
    #pragma unroll
    for (int i = 0; i < 4; ++i)
        dst[(size_t)(cot * 32 + r + 8 * i) * 256 + cit * 32 + c] = tf32r(t[c][r + 8 * i]);
}

// per-(b, 256-position chunk) partial {sum,sumsq} per co  (grid 512, block 256)
template <int WHICH>
__global__ __launch_bounds__(256)
void stats_kernel()
{
    const float* src = WHICH ? g_y2 : g_y1;
    const int bc = blockIdx.x;
    const int b = bc >> 7, ch = bc & 127;
    const int co = threadIdx.x & 127, h = threadIdx.x >> 7;
    const size_t base = ((size_t)b * 32768 + ch * 256 + h * 128) * 128;
    float s = 0.f, q = 0.f;
    for (int i = 0; i < 128; ++i) {
        const float v = src[base + (size_t)i * 128 + co];
        s += v; q += v * v;
    }
    __shared__ float2 red[256];
    red[threadIdx.x] = make_float2(s, q);
    __syncthreads();
    if (h == 0) {
        const float2 o = red[threadIdx.x + 128];
        g_part[(size_t)bc * 128 + co] = make_float2(s + o.x, q + o.y);
    }
}

template <int WHICH>
__global__ __launch_bounds__(128)
void finalize_kernel()
{
    const int co = blockIdx.x & 127, b = blockIdx.x >> 7;
    const int t = threadIdx.x;
    const float2 v = g_part[((size_t)b * 128 + t) * 128 + co];
    __shared__ float ss[128], qq[128];
    ss[t] = v.x; qq[t] = v.y;
    __syncthreads();
    for (int st = 64; st > 0; st >>= 1) {
        if (t < st) { ss[t] += ss[t + st]; qq[t] += qq[t + st]; }
        __syncthreads();
    }
    if (t == 0) {
        const float inv  = 1.0f / 32768.0f;
        const float mean = ss[0] * inv;
        const float var  = qq[0] * inv - mean * mean;
        const float2 mr  = make_float2(mean, rsqrtf(var + 1e-5f));
        if (WHICH == 0) g_mr1[b * 128 + co] = mr;
        else            g_mr2[b * 128 + co] = mr;
    }
}

// IN+ReLU on y1 -> padded g_pin2[:,0:128]; skip -> g_pin2[:,128:256] (tf32-rounded)
__global__ __launch_bounds__(256)
void norm1cat_kernel(const float* __restrict__ skip)
{
    const size_t i = (size_t)blockIdx.x * 256 + threadIdx.x;   // 8,388,608 float4s
    const int c4  = (int)(i & 63);
    const int pos = (int)((i >> 6) & 32767);
    const int b   = (int)(i >> 21);
    const int col = c4 * 4;
    float4 v;
    if (col < 128) {
        v = *(const float4*)&g_y1[((size_t)b * 32768 + pos) * 128 + col];
        const float2* mr = g_mr1 + b * 128 + col;
        const float2 m0 = mr[0], m1 = mr[1], m2 = mr[2], m3 = mr[3];
        v.x = fmaxf(0.f, (v.x - m0.x) * m0.y);
        v.y = fmaxf(0.f, (v.y - m1.x) * m1.y);
        v.z = fmaxf(0.f, (v.z - m2.x) * m2.y);
        v.w = fmaxf(0.f, (v.w - m3.x) * m3.y);
    } else {
        v = *(const float4*)&skip[((size_t)b * 32768 + pos) * 128 + (col - 128)];
    }
    v.x = tf32r(v.x); v.y = tf32r(v.y); v.z = tf32r(v.z); v.w = tf32r(v.w);
    const int z = pos >> 10, y = (pos >> 5) & 31, xx = pos & 31;
    const size_t sp = ((size_t)(z + 1) * 34 + (y + 1)) * 34 + (xx + 1);
    *(float4*)&g_pin2[((size_t)b * SP + sp) * 256 + col] = v;
}

// IN+ReLU on y2 -> out (full fp32, no rounding)
__global__ __launch_bounds__(256)
void norm2_kernel(float* __restrict__ out)
{
    const size_t idx = (size_t)blockIdx.x * 256 + threadIdx.x;
    const size_t e   = idx * 4;
    const int b  = (int)(e >> 22);
    const int co = (int)(e & 127);
    const float2* mr = g_mr2 + b * 128 + co;
    const float4 v = *(const float4*)&g_y2[e];
    const float2 m0 = mr[0], m1 = mr[1], m2 = mr[2], m3 = mr[3];
    float4 o;
    o.x = fmaxf(0.f, (v.x - m0.x) * m0.y);
    o.y = fmaxf(0.f, (v.y - m1.x) * m1.y);
    o.z = fmaxf(0.f, (v.z - m2.x) * m2.y);
    o.w = fmaxf(0.f, (v.w - m3.x) * m3.y);
    *(float4*)&out[e] = o;
}

// ===========================================================================
// host
// ===========================================================================
extern "C" void kernel_launch(void* const* d_in, const int* in_sizes, int n_in,
                              void* d_out, int out_size)
{
    const float* x    = (const float*)d_in[0];
    const float* w1   = (const float*)d_in[1];
    const float* w2   = (const float*)d_in[2];
    const float* skip = (const float*)d_in[3];
    float* out = (float*)d_out;
    (void)in_sizes; (void)n_in; (void)out_size;

    void *pin1 = nullptr, *pin2 = nullptr, *wT1 = nullptr, *wT2 = nullptr,
         *y1 = nullptr, *y2 = nullptr;
    if (cudaGetSymbolAddress(&pin1, g_pin1) != cudaSuccess) return;
    if (cudaGetSymbolAddress(&pin2, g_pin2) != cudaSuccess) return;
    if (cudaGetSymbolAddress(&wT1,  g_wT1)  != cudaSuccess) return;
    if (cudaGetSymbolAddress(&wT2,  g_wT2)  != cudaSuccess) return;
    if (cudaGetSymbolAddress(&y1,   g_y1)   != cudaSuccess) return;
    if (cudaGetSymbolAddress(&y2,   g_y2)   != cudaSuccess) return;

    static bool attr_done = false;
    if (!attr_done) {
        cudaFuncSetAttribute(conv_mma_kernel,
                             cudaFuncAttributeMaxDynamicSharedMemorySize,
                             SMEM_F * 4);
        attr_done = true;
    }

    pad1_kernel<<<32768, 256>>>(x);
    wtrans_kernel<<<3456, 256>>>(w1, (float*)wT1);
    wtrans_kernel<<<3456, 256>>>(w2, (float*)wT2);

    conv_mma_kernel<<<dim3(308, 4), 256, SMEM_F * 4>>>(
        (const float*)pin1, (const float*)wT1, (float*)y1);
    stats_kernel<0><<<512, 256>>>();
    finalize_kernel<0><<<512, 128>>>();
    norm1cat_kernel<<<32768, 256>>>(skip);

    conv_mma_kernel<<<dim3(308, 4), 256, SMEM_F * 4>>>(
        (const float*)pin2, (const float*)wT2, (float*)y2);
    stats_kernel<1><<<512, 256>>>();
    finalize_kernel<1><<<512, 128>>>();
    norm2_kernel<<<16384, 256>>>(out);
}